// round 2
// baseline (speedup 1.0000x reference)
#include <cuda_runtime.h>

// Problem constants (verified against reference setup_inputs)
#define LBATCH 32
#define DMV    16

// Scratch: per-l fused sandwich matrix S = Lmat@Rmat, and color-unit vectors.
__device__ float d_S [LBATCH][256];   // 32 KB
__device__ float d_bc[LBATCH][10];
__device__ float d_b0[LBATCH][10];

// Cayley sign for Cl(3,0,1): metric (+,+,+,0), bit k = e_k.
__device__ __forceinline__ float cayley_sign(int a, int b) {
    if (a & b & 8) return 0.0f;            // e3 * e3 = 0
    int s = 0;
    for (int t = a >> 1; t; t >>= 1) s += __popc(t & b);
    return (s & 1) ? -1.0f : 1.0f;
}

// ---------------------------------------------------------------------------
// Setup kernel: 32 blocks (one per l), 256 threads.
// Builds motor M = exp(-0.5*grade2(instr)) via 16-term Taylor, then
// S = Lmat @ Rmat (fused sandwich), and the collapsed color vectors bc,b0.
// ---------------------------------------------------------------------------
__global__ void setup_kernel(const float* __restrict__ instr,
                             const float* __restrict__ remap,   // [4,10,10]
                             const float* __restrict__ selw,    // [4,2]
                             const float* __restrict__ selb)    // [4]
{
    __shared__ float sgn[256];
    __shared__ float xv[16], term[16], acc[16], M[16], Mrev[16];
    __shared__ float Lm[256], Rm[256];
    __shared__ float w[4];

    const int l   = blockIdx.x;
    const int tid = threadIdx.x;
    const int a   = tid >> 4;
    const int b   = tid & 15;

    sgn[tid] = cayley_sign(a, b);

    if (tid < 16) {
        float iv = instr[l * DMV + tid];
        xv[tid]   = (__popc(tid) == 2) ? -0.5f * iv : 0.0f;  // grade-2 projection
        term[tid] = (tid == 0) ? 1.0f : 0.0f;
        acc[tid]  = term[tid];
    }
    __syncthreads();

    // Taylor exp: 15 sequential geometric products (matches reference n_terms=16)
    for (int n = 1; n < 16; n++) {
        float nt = 0.0f;
        if (tid < 16) {
            #pragma unroll
            for (int aa = 0; aa < 16; aa++)
                nt += term[aa] * xv[aa ^ tid] * sgn[aa * 16 + (aa ^ tid)];
            nt /= (float)n;
        }
        __syncthreads();
        if (tid < 16) { term[tid] = nt; acc[tid] += nt; }
        __syncthreads();
    }

    if (tid < 16) {
        M[tid] = acc[tid];
        int g = __popc(tid);
        float rv = (((g * (g - 1) / 2) & 1) != 0) ? -1.0f : 1.0f;  // reverse sign
        Mrev[tid] = acc[tid] * rv;
    }
    __syncthreads();

    // Lmat[j][k] = M[j^k]*sgn(j^k, j) ; Rmat[i][k] = Mrev[i^k]*sgn(i, i^k)
    Lm[tid] = M[a ^ b]   * sgn[(a ^ b) * 16 + a];
    Rm[tid] = Mrev[a ^ b] * sgn[a * 16 + (a ^ b)];
    __syncthreads();

    // S[j][k] = sum_i Lm[j][i] * Rm[i][k]
    {
        float s = 0.0f;
        #pragma unroll
        for (int i = 0; i < 16; i++)
            s += Lm[a * 16 + i] * Rm[i * 16 + b];
        d_S[l][tid] = s;
    }

    // Selector softmax over K=4 tables
    if (tid == 0) {
        float s0 = instr[l * DMV + 0], s1 = instr[l * DMV + 15];
        float lg[4], m = -3.4e38f;
        #pragma unroll
        for (int k = 0; k < 4; k++) {
            lg[k] = s0 * selw[k * 2 + 0] + s1 * selw[k * 2 + 1] + selb[k];
            m = fmaxf(m, lg[k]);
        }
        float sum = 0.0f;
        #pragma unroll
        for (int k = 0; k < 4; k++) { lg[k] = expf(lg[k] - m); sum += lg[k]; }
        #pragma unroll
        for (int k = 0; k < 4; k++) w[k] = lg[k] / sum;
    }
    __syncthreads();

    // Collapsed color vectors: bc[i] = sum_j blended[i][j]*j ; b0[i] = blended[i][0]
    if (tid < 10) {
        float bc = 0.0f, b0v = 0.0f;
        #pragma unroll
        for (int k = 0; k < 4; k++) {
            const float* tab = remap + k * 100 + tid * 10;
            float rowc = 0.0f;
            #pragma unroll
            for (int j = 0; j < 10; j++) rowc += tab[j] * (float)j;
            bc  += w[k] * rowc;
            b0v += w[k] * tab[0];
        }
        d_bc[l][tid] = bc;
        d_b0[l][tid] = b0v;
    }
}

// ---------------------------------------------------------------------------
// Main kernel: one thread per multivector row. Streaming, memory-bound.
// grid = (ceil(N/256), 32), block = 256.
// ---------------------------------------------------------------------------
__global__ void __launch_bounds__(256)
sandwich_color_kernel(const float* __restrict__ state,
                      float* __restrict__ out,
                      int N)
{
    __shared__ __align__(16) float Ssh[256];
    __shared__ float bcsh[10], b0sh[10];

    const int l   = blockIdx.y;
    const int tid = threadIdx.x;

    Ssh[tid] = d_S[l][tid];
    if (tid < 10) { bcsh[tid] = d_bc[l][tid]; b0sh[tid] = d_b0[l][tid]; }
    __syncthreads();

    const int n = blockIdx.x * 256 + tid;
    if (n >= N) return;

    const size_t base = ((size_t)l * N + n) * DMV;
    const float4* xp = reinterpret_cast<const float4*>(state + base);
    float4 v0 = xp[0], v1 = xp[1], v2 = xp[2], v3 = xp[3];
    float x[16] = { v0.x, v0.y, v0.z, v0.w,
                    v1.x, v1.y, v1.z, v1.w,
                    v2.x, v2.y, v2.z, v2.w,
                    v3.x, v3.y, v3.z, v3.w };

    float y[16];
    #pragma unroll
    for (int k = 0; k < 16; k++) y[k] = 0.0f;

    const float4* S4 = reinterpret_cast<const float4*>(Ssh);
    #pragma unroll
    for (int j = 0; j < 16; j++) {
        float xj = x[j];
        float4 s0 = S4[j * 4 + 0];
        float4 s1 = S4[j * 4 + 1];
        float4 s2 = S4[j * 4 + 2];
        float4 s3 = S4[j * 4 + 3];
        y[0]  = fmaf(xj, s0.x, y[0]);  y[1]  = fmaf(xj, s0.y, y[1]);
        y[2]  = fmaf(xj, s0.z, y[2]);  y[3]  = fmaf(xj, s0.w, y[3]);
        y[4]  = fmaf(xj, s1.x, y[4]);  y[5]  = fmaf(xj, s1.y, y[5]);
        y[6]  = fmaf(xj, s1.z, y[6]);  y[7]  = fmaf(xj, s1.w, y[7]);
        y[8]  = fmaf(xj, s2.x, y[8]);  y[9]  = fmaf(xj, s2.y, y[9]);
        y[10] = fmaf(xj, s2.z, y[10]); y[11] = fmaf(xj, s2.w, y[11]);
        y[12] = fmaf(xj, s3.x, y[12]); y[13] = fmaf(xj, s3.y, y[13]);
        y[14] = fmaf(xj, s3.z, y[14]); y[15] = fmaf(xj, s3.w, y[15]);
    }

    // Collapsed color unit: softmax over 10 centers, only color/occ outputs needed.
    float raw = y[0] * 9.0f;
    float lg[10], m = -3.4e38f;
    #pragma unroll
    for (int i = 0; i < 10; i++) {
        float t = raw - (float)i;
        lg[i] = -4.0f * t * t;
        m = fmaxf(m, lg[i]);
    }
    float se = 0.0f, nc = 0.0f, n0 = 0.0f;
    #pragma unroll
    for (int i = 0; i < 10; i++) {
        float e = __expf(lg[i] - m);
        se += e;
        nc = fmaf(e, bcsh[i], nc);
        n0 = fmaf(e, b0sh[i], n0);
    }
    float inv = 1.0f / se;
    y[0]  = nc * inv * (1.0f / 9.0f);
    y[15] = 1.0f - n0 * inv;

    float4* op = reinterpret_cast<float4*>(out + base);
    op[0] = make_float4(y[0],  y[1],  y[2],  y[3]);
    op[1] = make_float4(y[4],  y[5],  y[6],  y[7]);
    op[2] = make_float4(y[8],  y[9],  y[10], y[11]);
    op[3] = make_float4(y[12], y[13], y[14], y[15]);
}

extern "C" void kernel_launch(void* const* d_in, const int* in_sizes, int n_in,
                              void* d_out, int out_size)
{
    const float* state = (const float*)d_in[0];
    const float* instr = (const float*)d_in[1];
    const float* remap = (const float*)d_in[2];
    const float* selw  = (const float*)d_in[3];
    const float* selb  = (const float*)d_in[4];
    float* out = (float*)d_out;

    const int N = in_sizes[0] / (LBATCH * DMV);   // 100000

    setup_kernel<<<LBATCH, 256>>>(instr, remap, selw, selb);

    dim3 grid((N + 255) / 256, LBATCH);
    sandwich_color_kernel<<<grid, 256>>>(state, out, N);
}

// round 3
// speedup vs baseline: 1.4096x; 1.4096x over previous
#include <cuda_runtime.h>

#define LBATCH 32
#define DMV    16

// Packed per-l constants, 112 floats each:
//  [0:16)   G1 block col-major  (inputs/outputs idx {1,2,4,8})
//  [16:64)  G2 block col-major, cols padded to 8 (idx {3,5,6,9,10,12})
//  [64:80)  G3 block col-major  (idx {7,11,13,14})
//  [80:90)  bc (pad to 96)
//  [96:106) b0 (pad to 112)
__device__ float d_P[LBATCH][112];

__device__ __forceinline__ float cayley_sign(int a, int b) {
    if (a & b & 8) return 0.0f;            // e3 * e3 = 0
    int s = 0;
    for (int t = a >> 1; t; t >>= 1) s += __popc(t & b);
    return (s & 1) ? -1.0f : 1.0f;
}

// ---------------------------------------------------------------------------
// Setup: 32 blocks (one per l), 256 threads. Motor exp -> fused sandwich S ->
// grade-block packing + collapsed color vectors.
// ---------------------------------------------------------------------------
__global__ void setup_kernel(const float* __restrict__ instr,
                             const float* __restrict__ remap,   // [4,10,10]
                             const float* __restrict__ selw,    // [4,2]
                             const float* __restrict__ selb)    // [4]
{
    __shared__ float sgn[256];
    __shared__ float xv[16], term[16], acc[16], M[16], Mrev[16];
    __shared__ float Lm[256], Rm[256], Sb[256];
    __shared__ float w[4];

    const int l   = blockIdx.x;
    const int tid = threadIdx.x;
    const int a   = tid >> 4;
    const int b   = tid & 15;

    sgn[tid] = cayley_sign(a, b);

    if (tid < 16) {
        float iv = instr[l * DMV + tid];
        xv[tid]   = (__popc(tid) == 2) ? -0.5f * iv : 0.0f;
        term[tid] = (tid == 0) ? 1.0f : 0.0f;
        acc[tid]  = term[tid];
    }
    __syncthreads();

    for (int n = 1; n < 16; n++) {
        float nt = 0.0f;
        if (tid < 16) {
            #pragma unroll
            for (int aa = 0; aa < 16; aa++)
                nt += term[aa] * xv[aa ^ tid] * sgn[aa * 16 + (aa ^ tid)];
            nt /= (float)n;
        }
        __syncthreads();
        if (tid < 16) { term[tid] = nt; acc[tid] += nt; }
        __syncthreads();
    }

    if (tid < 16) {
        M[tid] = acc[tid];
        int g = __popc(tid);
        float rv = (((g * (g - 1) / 2) & 1) != 0) ? -1.0f : 1.0f;
        Mrev[tid] = acc[tid] * rv;
    }
    __syncthreads();

    Lm[tid] = M[a ^ b]    * sgn[(a ^ b) * 16 + a];
    Rm[tid] = Mrev[a ^ b] * sgn[a * 16 + (a ^ b)];
    __syncthreads();

    {   // S[j][k] = sum_i Lm[j][i] * Rm[i][k]  (y_k = sum_j x_j S[j][k])
        float s = 0.0f;
        #pragma unroll
        for (int i = 0; i < 16; i++)
            s += Lm[a * 16 + i] * Rm[i * 16 + b];
        Sb[tid] = s;
    }

    if (tid == 0) {
        float s0 = instr[l * DMV + 0], s1 = instr[l * DMV + 15];
        float lg[4], m = -3.4e38f;
        #pragma unroll
        for (int k = 0; k < 4; k++) {
            lg[k] = s0 * selw[k * 2 + 0] + s1 * selw[k * 2 + 1] + selb[k];
            m = fmaxf(m, lg[k]);
        }
        float sum = 0.0f;
        #pragma unroll
        for (int k = 0; k < 4; k++) { lg[k] = expf(lg[k] - m); sum += lg[k]; }
        #pragma unroll
        for (int k = 0; k < 4; k++) w[k] = lg[k] / sum;
    }
    __syncthreads();

    const int g1[4] = {1, 2, 4, 8};
    const int g2[6] = {3, 5, 6, 9, 10, 12};
    const int g3[4] = {7, 11, 13, 14};

    if (tid < 16) {                       // G1 col-major: [j*4+i]
        int j = tid >> 2, i = tid & 3;
        d_P[l][tid] = Sb[g1[j] * 16 + g1[i]];
    } else if (tid < 64) {                // G2 col-major, cols padded to 8
        int t = tid - 16, j = t >> 3, i = t & 7;
        d_P[l][16 + t] = (i < 6) ? Sb[g2[j] * 16 + g2[i]] : 0.0f;
    } else if (tid < 80) {                // G3
        int t = tid - 64, j = t >> 2, i = t & 3;
        d_P[l][64 + t] = Sb[g3[j] * 16 + g3[i]];
    } else if (tid < 112) {
        d_P[l][tid] = 0.0f;               // zero bc/b0 region incl. pads
    }
    __syncthreads();

    if (tid < 10) {                       // collapsed color vectors
        float bc = 0.0f, b0v = 0.0f;
        #pragma unroll
        for (int k = 0; k < 4; k++) {
            const float* tab = remap + k * 100 + tid * 10;
            float rowc = 0.0f;
            #pragma unroll
            for (int j = 0; j < 10; j++) rowc += tab[j] * (float)j;
            bc  += w[k] * rowc;
            b0v += w[k] * tab[0];
        }
        d_P[l][80 + tid] = bc;
        d_P[l][96 + tid] = b0v;
    }
}

// ---------------------------------------------------------------------------
// Main kernel: one thread per row. Grade-block matvec (68 FMA) + color unit.
// ---------------------------------------------------------------------------
__global__ void __launch_bounds__(256)
sandwich_color_kernel(const float* __restrict__ state,
                      float* __restrict__ out,
                      int N)
{
    __shared__ __align__(16) float P[112];
    const int l   = blockIdx.y;
    const int tid = threadIdx.x;

    if (tid < 112) P[tid] = d_P[l][tid];
    __syncthreads();

    const int n = blockIdx.x * 256 + tid;
    if (n >= N) return;

    const size_t base = ((size_t)l * N + n) * DMV;
    const float4* xp = reinterpret_cast<const float4*>(state + base);
    float4 v0 = xp[0], v1 = xp[1], v2 = xp[2], v3 = xp[3];

    const float x0 = v0.x, x1 = v0.y, x2  = v0.z, x3  = v0.w;
    const float x4 = v1.x, x5 = v1.y, x6  = v1.z, x7  = v1.w;
    const float x8 = v2.x, x9 = v2.y, x10 = v2.z, x11 = v2.w;
    const float x12 = v3.x, x13 = v3.y, x14 = v3.z;   // x15 unused (overwritten)

    const float4* P4 = reinterpret_cast<const float4*>(P);

    // grade-1 block (outputs y1,y2,y4,y8)
    float4 a0 = P4[0], a1 = P4[1], a2 = P4[2], a3 = P4[3];
    float y1 = fmaf(x8, a3.x, fmaf(x4, a2.x, fmaf(x2, a1.x, x1 * a0.x)));
    float y2 = fmaf(x8, a3.y, fmaf(x4, a2.y, fmaf(x2, a1.y, x1 * a0.y)));
    float y4 = fmaf(x8, a3.z, fmaf(x4, a2.z, fmaf(x2, a1.z, x1 * a0.z)));
    float y8 = fmaf(x8, a3.w, fmaf(x4, a2.w, fmaf(x2, a1.w, x1 * a0.w)));

    // grade-2 block (inputs/outputs 3,5,6,9,10,12)
    float y3, y5, y6, y9, y10, y12;
    {
        float4 cA = P4[4], cB = P4[5];
        y3 = x3 * cA.x; y5 = x3 * cA.y; y6  = x3 * cA.z;
        y9 = x3 * cA.w; y10 = x3 * cB.x; y12 = x3 * cB.y;
    }
    {
        float4 cA = P4[6], cB = P4[7];
        y3 = fmaf(x5, cA.x, y3); y5  = fmaf(x5, cA.y, y5);  y6  = fmaf(x5, cA.z, y6);
        y9 = fmaf(x5, cA.w, y9); y10 = fmaf(x5, cB.x, y10); y12 = fmaf(x5, cB.y, y12);
    }
    {
        float4 cA = P4[8], cB = P4[9];
        y3 = fmaf(x6, cA.x, y3); y5  = fmaf(x6, cA.y, y5);  y6  = fmaf(x6, cA.z, y6);
        y9 = fmaf(x6, cA.w, y9); y10 = fmaf(x6, cB.x, y10); y12 = fmaf(x6, cB.y, y12);
    }
    {
        float4 cA = P4[10], cB = P4[11];
        y3 = fmaf(x9, cA.x, y3); y5  = fmaf(x9, cA.y, y5);  y6  = fmaf(x9, cA.z, y6);
        y9 = fmaf(x9, cA.w, y9); y10 = fmaf(x9, cB.x, y10); y12 = fmaf(x9, cB.y, y12);
    }
    {
        float4 cA = P4[12], cB = P4[13];
        y3 = fmaf(x10, cA.x, y3); y5  = fmaf(x10, cA.y, y5);  y6  = fmaf(x10, cA.z, y6);
        y9 = fmaf(x10, cA.w, y9); y10 = fmaf(x10, cB.x, y10); y12 = fmaf(x10, cB.y, y12);
    }
    {
        float4 cA = P4[14], cB = P4[15];
        y3 = fmaf(x12, cA.x, y3); y5  = fmaf(x12, cA.y, y5);  y6  = fmaf(x12, cA.z, y6);
        y9 = fmaf(x12, cA.w, y9); y10 = fmaf(x12, cB.x, y10); y12 = fmaf(x12, cB.y, y12);
    }

    // grade-3 block (outputs y7,y11,y13,y14)
    float4 h0 = P4[16], h1 = P4[17], h2 = P4[18], h3 = P4[19];
    float y7  = fmaf(x14, h3.x, fmaf(x13, h2.x, fmaf(x11, h1.x, x7 * h0.x)));
    float y11 = fmaf(x14, h3.y, fmaf(x13, h2.y, fmaf(x11, h1.y, x7 * h0.y)));
    float y13 = fmaf(x14, h3.z, fmaf(x13, h2.z, fmaf(x11, h1.z, x7 * h0.z)));
    float y14 = fmaf(x14, h3.w, fmaf(x13, h2.w, fmaf(x11, h1.w, x7 * h0.w)));

    // color unit from x0 (y0 == x0 since M~M = 1; grade preserved)
    float4 bcA = P4[20], bcB = P4[21], bcC = P4[22];
    float4 b0A = P4[24], b0B = P4[25], b0C = P4[26];
    const float bcr[10] = { bcA.x, bcA.y, bcA.z, bcA.w, bcB.x, bcB.y, bcB.z, bcB.w, bcC.x, bcC.y };
    const float b0r[10] = { b0A.x, b0A.y, b0A.z, b0A.w, b0B.x, b0B.y, b0B.z, b0B.w, b0C.x, b0C.y };

    float raw = x0 * 9.0f;
    float c = fminf(fmaxf(rintf(raw), 0.0f), 9.0f);
    float dm = raw - c;
    float m = -4.0f * dm * dm;                  // exact max of the 10 logits
    float se = 0.0f, nc = 0.0f, n0 = 0.0f;
    #pragma unroll
    for (int i = 0; i < 10; i++) {
        float t = raw - (float)i;
        float e = __expf(fmaf(-4.0f * t, t, -m));
        se += e;
        nc = fmaf(e, bcr[i], nc);
        n0 = fmaf(e, b0r[i], n0);
    }
    float inv = 1.0f / se;
    float out0  = nc * inv * (1.0f / 9.0f);
    float out15 = 1.0f - n0 * inv;

    float4* op = reinterpret_cast<float4*>(out + base);
    op[0] = make_float4(out0, y1,  y2,  y3);
    op[1] = make_float4(y4,   y5,  y6,  y7);
    op[2] = make_float4(y8,   y9,  y10, y11);
    op[3] = make_float4(y12,  y13, y14, out15);
}

extern "C" void kernel_launch(void* const* d_in, const int* in_sizes, int n_in,
                              void* d_out, int out_size)
{
    const float* state = (const float*)d_in[0];
    const float* instr = (const float*)d_in[1];
    const float* remap = (const float*)d_in[2];
    const float* selw  = (const float*)d_in[3];
    const float* selb  = (const float*)d_in[4];
    float* out = (float*)d_out;

    const int N = in_sizes[0] / (LBATCH * DMV);   // 100000

    setup_kernel<<<LBATCH, 256>>>(instr, remap, selw, selb);

    dim3 grid((N + 255) / 256, LBATCH);
    sandwich_color_kernel<<<grid, 256>>>(state, out, N);
}

// round 4
// speedup vs baseline: 1.5062x; 1.0685x over previous
#include <cuda_runtime.h>

#define LBATCH 32
#define DMV    16
#define TILE   256

// Packed per-l constants, 112 floats each:
//  [0:16)   G1 block col-major  (idx {1,2,4,8})
//  [16:64)  G2 block col-major, cols padded to 8 (idx {3,5,6,9,10,12})
//  [64:80)  G3 block col-major  (idx {7,11,13,14})
//  [80:90)  bc (pad to 96)   [96:106) b0 (pad to 112)
__device__ float d_P[LBATCH][112];

__device__ __forceinline__ float cayley_sign(int a, int b) {
    if (a & b & 8) return 0.0f;            // e3 * e3 = 0
    int s = 0;
    for (int t = a >> 1; t; t >>= 1) s += __popc(t & b);
    return (s & 1) ? -1.0f : 1.0f;
}

// ---------------------------------------------------------------------------
// Setup: 32 blocks, 256 threads. Warp-shuffle Taylor (no per-iter block sync).
// ---------------------------------------------------------------------------
__global__ void setup_kernel(const float* __restrict__ instr,
                             const float* __restrict__ remap,   // [4,10,10]
                             const float* __restrict__ selw,    // [4,2]
                             const float* __restrict__ selb)    // [4]
{
    __shared__ float sgn[256];
    __shared__ float M[16], Mrev[16];
    __shared__ float Lm[256], Rm[256], Sb[256];
    __shared__ float w[4];

    const int l   = blockIdx.x;
    const int tid = threadIdx.x;
    const int a   = tid >> 4;
    const int b   = tid & 15;

    sgn[tid] = cayley_sign(a, b);
    __syncthreads();

    // Taylor exp on lanes 0..15 of warp 0, shuffle-based (no block barriers)
    if (tid < 16) {
        const unsigned mask = 0x0000FFFFu;
        float iv   = instr[l * DMV + tid];
        float xv   = (__popc(tid) == 2) ? -0.5f * iv : 0.0f;
        float term = (tid == 0) ? 1.0f : 0.0f;
        float acc  = term;
        for (int n = 1; n < 16; n++) {
            float nt = 0.0f;
            #pragma unroll
            for (int aa = 0; aa < 16; aa++) {
                float ta = __shfl_sync(mask, term, aa);
                float xa = __shfl_sync(mask, xv, aa ^ tid);
                nt += ta * xa * sgn[aa * 16 + (aa ^ tid)];
            }
            term = nt / (float)n;
            acc += term;
        }
        M[tid] = acc;
        int g = __popc(tid);
        float rv = (((g * (g - 1) / 2) & 1) != 0) ? -1.0f : 1.0f;
        Mrev[tid] = acc * rv;
    }
    __syncthreads();

    Lm[tid] = M[a ^ b]    * sgn[(a ^ b) * 16 + a];
    Rm[tid] = Mrev[a ^ b] * sgn[a * 16 + (a ^ b)];
    __syncthreads();

    {   // S[j][k] = sum_i Lm[j][i] * Rm[i][k]
        float s = 0.0f;
        #pragma unroll
        for (int i = 0; i < 16; i++)
            s += Lm[a * 16 + i] * Rm[i * 16 + b];
        Sb[tid] = s;
    }

    if (tid == 0) {
        float s0 = instr[l * DMV + 0], s1 = instr[l * DMV + 15];
        float lg[4], m = -3.4e38f;
        #pragma unroll
        for (int k = 0; k < 4; k++) {
            lg[k] = s0 * selw[k * 2 + 0] + s1 * selw[k * 2 + 1] + selb[k];
            m = fmaxf(m, lg[k]);
        }
        float sum = 0.0f;
        #pragma unroll
        for (int k = 0; k < 4; k++) { lg[k] = expf(lg[k] - m); sum += lg[k]; }
        #pragma unroll
        for (int k = 0; k < 4; k++) w[k] = lg[k] / sum;
    }
    __syncthreads();

    const int g1[4] = {1, 2, 4, 8};
    const int g2[6] = {3, 5, 6, 9, 10, 12};
    const int g3[4] = {7, 11, 13, 14};

    if (tid < 16) {
        int j = tid >> 2, i = tid & 3;
        d_P[l][tid] = Sb[g1[j] * 16 + g1[i]];
    } else if (tid < 64) {
        int t = tid - 16, j = t >> 3, i = t & 7;
        d_P[l][16 + t] = (i < 6) ? Sb[g2[j] * 16 + g2[i]] : 0.0f;
    } else if (tid < 80) {
        int t = tid - 64, j = t >> 2, i = t & 3;
        d_P[l][64 + t] = Sb[g3[j] * 16 + g3[i]];
    } else if (tid < 112) {
        d_P[l][tid] = 0.0f;
    }

    if (tid < 10) {
        float bc = 0.0f, b0v = 0.0f;
        #pragma unroll
        for (int k = 0; k < 4; k++) {
            const float* tab = remap + k * 100 + tid * 10;
            float rowc = 0.0f;
            #pragma unroll
            for (int j = 0; j < 10; j++) rowc += tab[j] * (float)j;
            bc  += w[k] * rowc;
            b0v += w[k] * tab[0];
        }
        d_P[l][80 + tid] = bc;
        d_P[l][96 + tid] = b0v;
    }
}

// ---------------------------------------------------------------------------
// Main kernel: coalesced global <-> swizzled SMEM tile, one row per thread.
// Swizzle: row r, float4-col c stored at col (c ^ ((r>>1)&3)).
//   - staging STS (coalesced src, lanes cover 2 rows/phase) conflict-free
//   - per-row LDS/STS (4 lanes per 32-bank base get distinct cols) conflict-free
// ---------------------------------------------------------------------------
__global__ void __launch_bounds__(256)
sandwich_color_kernel(const float* __restrict__ state,
                      float* __restrict__ out,
                      int N)
{
    __shared__ __align__(16) float4 buf[TILE * 4];   // 16 KB
    __shared__ __align__(16) float P[112];

    const int l    = blockIdx.y;
    const int tid  = threadIdx.x;
    const int tile0 = blockIdx.x * TILE;
    const int nvalid = min(TILE, N - tile0);

    if (tid < 112) P[tid] = d_P[l][tid];

    const size_t gbase4 = ((size_t)l * N + tile0) * 4;   // float4 units
    const float4* gin  = reinterpret_cast<const float4*>(state) + gbase4;
    float4*       gout = reinterpret_cast<float4*>(out)   + gbase4;

    // stage in (coalesced LDG -> swizzled STS)
    #pragma unroll
    for (int k = 0; k < 4; k++) {
        int e = k * TILE + tid;
        int r = e >> 2, c = e & 3;
        float4 v = (r < nvalid) ? gin[e] : make_float4(0.f, 0.f, 0.f, 0.f);
        buf[r * 4 + (c ^ ((r >> 1) & 3))] = v;
    }
    __syncthreads();

    {
        const int r  = tid;
        const int sw = (r >> 1) & 3;
        float4 v0 = buf[r * 4 + (0 ^ sw)];
        float4 v1 = buf[r * 4 + (1 ^ sw)];
        float4 v2 = buf[r * 4 + (2 ^ sw)];
        float4 v3 = buf[r * 4 + (3 ^ sw)];

        const float x0 = v0.x, x1 = v0.y, x2  = v0.z, x3  = v0.w;
        const float x4 = v1.x, x5 = v1.y, x6  = v1.z, x7  = v1.w;
        const float x8 = v2.x, x9 = v2.y, x10 = v2.z, x11 = v2.w;
        const float x12 = v3.x, x13 = v3.y, x14 = v3.z;   // x15 unused

        const float4* P4 = reinterpret_cast<const float4*>(P);

        // grade-1 block
        float4 a0 = P4[0], a1 = P4[1], a2 = P4[2], a3 = P4[3];
        float y1 = fmaf(x8, a3.x, fmaf(x4, a2.x, fmaf(x2, a1.x, x1 * a0.x)));
        float y2 = fmaf(x8, a3.y, fmaf(x4, a2.y, fmaf(x2, a1.y, x1 * a0.y)));
        float y4 = fmaf(x8, a3.z, fmaf(x4, a2.z, fmaf(x2, a1.z, x1 * a0.z)));
        float y8 = fmaf(x8, a3.w, fmaf(x4, a2.w, fmaf(x2, a1.w, x1 * a0.w)));

        // grade-2 block
        float y3, y5, y6, y9, y10, y12;
        {
            float4 cA = P4[4], cB = P4[5];
            y3 = x3 * cA.x; y5 = x3 * cA.y; y6  = x3 * cA.z;
            y9 = x3 * cA.w; y10 = x3 * cB.x; y12 = x3 * cB.y;
        }
        {
            float4 cA = P4[6], cB = P4[7];
            y3 = fmaf(x5, cA.x, y3); y5  = fmaf(x5, cA.y, y5);  y6  = fmaf(x5, cA.z, y6);
            y9 = fmaf(x5, cA.w, y9); y10 = fmaf(x5, cB.x, y10); y12 = fmaf(x5, cB.y, y12);
        }
        {
            float4 cA = P4[8], cB = P4[9];
            y3 = fmaf(x6, cA.x, y3); y5  = fmaf(x6, cA.y, y5);  y6  = fmaf(x6, cA.z, y6);
            y9 = fmaf(x6, cA.w, y9); y10 = fmaf(x6, cB.x, y10); y12 = fmaf(x6, cB.y, y12);
        }
        {
            float4 cA = P4[10], cB = P4[11];
            y3 = fmaf(x9, cA.x, y3); y5  = fmaf(x9, cA.y, y5);  y6  = fmaf(x9, cA.z, y6);
            y9 = fmaf(x9, cA.w, y9); y10 = fmaf(x9, cB.x, y10); y12 = fmaf(x9, cB.y, y12);
        }
        {
            float4 cA = P4[12], cB = P4[13];
            y3 = fmaf(x10, cA.x, y3); y5  = fmaf(x10, cA.y, y5);  y6  = fmaf(x10, cA.z, y6);
            y9 = fmaf(x10, cA.w, y9); y10 = fmaf(x10, cB.x, y10); y12 = fmaf(x10, cB.y, y12);
        }
        {
            float4 cA = P4[14], cB = P4[15];
            y3 = fmaf(x12, cA.x, y3); y5  = fmaf(x12, cA.y, y5);  y6  = fmaf(x12, cA.z, y6);
            y9 = fmaf(x12, cA.w, y9); y10 = fmaf(x12, cB.x, y10); y12 = fmaf(x12, cB.y, y12);
        }

        // grade-3 block
        float4 h0 = P4[16], h1 = P4[17], h2 = P4[18], h3 = P4[19];
        float y7  = fmaf(x14, h3.x, fmaf(x13, h2.x, fmaf(x11, h1.x, x7 * h0.x)));
        float y11 = fmaf(x14, h3.y, fmaf(x13, h2.y, fmaf(x11, h1.y, x7 * h0.y)));
        float y13 = fmaf(x14, h3.z, fmaf(x13, h2.z, fmaf(x11, h1.z, x7 * h0.z)));
        float y14 = fmaf(x14, h3.w, fmaf(x13, h2.w, fmaf(x11, h1.w, x7 * h0.w)));

        // color unit from x0 (y0 == x0: M~M = 1, grade preserved)
        float4 bcA = P4[20], bcB = P4[21], bcC = P4[22];
        float4 b0A = P4[24], b0B = P4[25], b0C = P4[26];
        const float bcr[10] = { bcA.x, bcA.y, bcA.z, bcA.w, bcB.x, bcB.y, bcB.z, bcB.w, bcC.x, bcC.y };
        const float b0r[10] = { b0A.x, b0A.y, b0A.z, b0A.w, b0B.x, b0B.y, b0B.z, b0B.w, b0C.x, b0C.y };

        float raw = x0 * 9.0f;
        float cc = fminf(fmaxf(rintf(raw), 0.0f), 9.0f);
        float dm = raw - cc;
        float m = -4.0f * dm * dm;                  // exact max of the 10 logits
        float se = 0.0f, nc = 0.0f, n0 = 0.0f;
        #pragma unroll
        for (int i = 0; i < 10; i++) {
            float t = raw - (float)i;
            float e = __expf(fmaf(-4.0f * t, t, -m));
            se += e;
            nc = fmaf(e, bcr[i], nc);
            n0 = fmaf(e, b0r[i], n0);
        }
        float inv = 1.0f / se;
        float out0  = nc * inv * (1.0f / 9.0f);
        float out15 = 1.0f - n0 * inv;

        // write own row back (exclusive ownership: no barrier needed here)
        buf[r * 4 + (0 ^ sw)] = make_float4(out0, y1,  y2,  y3);
        buf[r * 4 + (1 ^ sw)] = make_float4(y4,   y5,  y6,  y7);
        buf[r * 4 + (2 ^ sw)] = make_float4(y8,   y9,  y10, y11);
        buf[r * 4 + (3 ^ sw)] = make_float4(y12,  y13, y14, out15);
    }
    __syncthreads();

    // stage out (swizzled LDS -> coalesced STG)
    #pragma unroll
    for (int k = 0; k < 4; k++) {
        int e = k * TILE + tid;
        int r = e >> 2, c = e & 3;
        if (r < nvalid) gout[e] = buf[r * 4 + (c ^ ((r >> 1) & 3))];
    }
}

extern "C" void kernel_launch(void* const* d_in, const int* in_sizes, int n_in,
                              void* d_out, int out_size)
{
    const float* state = (const float*)d_in[0];
    const float* instr = (const float*)d_in[1];
    const float* remap = (const float*)d_in[2];
    const float* selw  = (const float*)d_in[3];
    const float* selb  = (const float*)d_in[4];
    float* out = (float*)d_out;

    const int N = in_sizes[0] / (LBATCH * DMV);   // 100000

    setup_kernel<<<LBATCH, 256>>>(instr, remap, selw, selb);

    dim3 grid((N + TILE - 1) / TILE, LBATCH);
    sandwich_color_kernel<<<grid, 256>>>(state, out, N);
}

// round 5
// speedup vs baseline: 1.6401x; 1.0889x over previous
#include <cuda_runtime.h>
#include <cstdint>

#define LBATCH 32
#define DMV    16
#define TILE   256

// Packed per-l constants, 112 floats each:
//  [0:16)   G1 block col-major  (idx {1,2,4,8})
//  [16:64)  G2 block col-major, cols padded to 8 (idx {3,5,6,9,10,12})
//  [64:80)  G3 block col-major  (idx {7,11,13,14})
//  [80:90)  bc (pad to 96)   [96:106) b0 (pad to 112)
__device__ float d_P[LBATCH][112];

__device__ __forceinline__ float cayley_sign(int a, int b) {
    if (a & b & 8) return 0.0f;            // e3 * e3 = 0
    int s = 0;
    for (int t = a >> 1; t; t >>= 1) s += __popc(t & b);
    return (s & 1) ? -1.0f : 1.0f;
}

__device__ __forceinline__ uint32_t smem_u32(const void* p) {
    return (uint32_t)__cvta_generic_to_shared(p);
}
__device__ __forceinline__ void cp_async16(uint32_t saddr, const void* gptr) {
    asm volatile("cp.async.cg.shared.global [%0], [%1], 16;" :: "r"(saddr), "l"(gptr));
}

// ---------------------------------------------------------------------------
// Setup: 32 blocks, 256 threads. Warp-shuffle Taylor exp -> fused sandwich ->
// grade-block packing + collapsed color vectors.
// ---------------------------------------------------------------------------
__global__ void setup_kernel(const float* __restrict__ instr,
                             const float* __restrict__ remap,   // [4,10,10]
                             const float* __restrict__ selw,    // [4,2]
                             const float* __restrict__ selb)    // [4]
{
    __shared__ float sgn[256];
    __shared__ float M[16], Mrev[16];
    __shared__ float Lm[256], Rm[256], Sb[256];
    __shared__ float w[4];

    const int l   = blockIdx.x;
    const int tid = threadIdx.x;
    const int a   = tid >> 4;
    const int b   = tid & 15;

    sgn[tid] = cayley_sign(a, b);
    __syncthreads();

    if (tid < 16) {
        const unsigned mask = 0x0000FFFFu;
        float iv   = instr[l * DMV + tid];
        float xv   = (__popc(tid) == 2) ? -0.5f * iv : 0.0f;
        float term = (tid == 0) ? 1.0f : 0.0f;
        float acc  = term;
        for (int n = 1; n < 16; n++) {
            float nt = 0.0f;
            #pragma unroll
            for (int aa = 0; aa < 16; aa++) {
                float ta = __shfl_sync(mask, term, aa);
                float xa = __shfl_sync(mask, xv, aa ^ tid);
                nt += ta * xa * sgn[aa * 16 + (aa ^ tid)];
            }
            term = nt / (float)n;
            acc += term;
        }
        M[tid] = acc;
        int g = __popc(tid);
        float rv = (((g * (g - 1) / 2) & 1) != 0) ? -1.0f : 1.0f;
        Mrev[tid] = acc * rv;
    }
    __syncthreads();

    Lm[tid] = M[a ^ b]    * sgn[(a ^ b) * 16 + a];
    Rm[tid] = Mrev[a ^ b] * sgn[a * 16 + (a ^ b)];
    __syncthreads();

    {
        float s = 0.0f;
        #pragma unroll
        for (int i = 0; i < 16; i++)
            s += Lm[a * 16 + i] * Rm[i * 16 + b];
        Sb[tid] = s;
    }

    if (tid == 0) {
        float s0 = instr[l * DMV + 0], s1 = instr[l * DMV + 15];
        float lg[4], m = -3.4e38f;
        #pragma unroll
        for (int k = 0; k < 4; k++) {
            lg[k] = s0 * selw[k * 2 + 0] + s1 * selw[k * 2 + 1] + selb[k];
            m = fmaxf(m, lg[k]);
        }
        float sum = 0.0f;
        #pragma unroll
        for (int k = 0; k < 4; k++) { lg[k] = expf(lg[k] - m); sum += lg[k]; }
        #pragma unroll
        for (int k = 0; k < 4; k++) w[k] = lg[k] / sum;
    }
    __syncthreads();

    const int g1[4] = {1, 2, 4, 8};
    const int g2[6] = {3, 5, 6, 9, 10, 12};
    const int g3[4] = {7, 11, 13, 14};

    if (tid < 16) {
        int j = tid >> 2, i = tid & 3;
        d_P[l][tid] = Sb[g1[j] * 16 + g1[i]];
    } else if (tid < 64) {
        int t = tid - 16, j = t >> 3, i = t & 7;
        d_P[l][16 + t] = (i < 6) ? Sb[g2[j] * 16 + g2[i]] : 0.0f;
    } else if (tid < 80) {
        int t = tid - 64, j = t >> 2, i = t & 3;
        d_P[l][64 + t] = Sb[g3[j] * 16 + g3[i]];
    } else if (tid < 112) {
        d_P[l][tid] = 0.0f;
    }

    if (tid < 10) {
        float bc = 0.0f, b0v = 0.0f;
        #pragma unroll
        for (int k = 0; k < 4; k++) {
            const float* tab = remap + k * 100 + tid * 10;
            float rowc = 0.0f;
            #pragma unroll
            for (int j = 0; j < 10; j++) rowc += tab[j] * (float)j;
            bc  += w[k] * rowc;
            b0v += w[k] * tab[0];
        }
        d_P[l][80 + tid] = bc;
        d_P[l][96 + tid] = b0v;
    }
}

// ---------------------------------------------------------------------------
// Main kernel: cp.async coalesced stage-in -> swizzled SMEM -> per-row compute
// -> swizzled SMEM -> coalesced streaming STG. One row per thread.
// Swizzle: row r, float4-col c at col (c ^ ((r>>1)&3)) — conflict-free both ways.
// ---------------------------------------------------------------------------
__global__ void __launch_bounds__(256, 6)
sandwich_color_kernel(const float* __restrict__ state,
                      float* __restrict__ out,
                      int N)
{
    __shared__ __align__(16) float4 buf[TILE * 4];   // 16 KB
    __shared__ __align__(16) float P[112];

    const int l     = blockIdx.y;
    const int tid   = threadIdx.x;
    const int tile0 = blockIdx.x * TILE;
    const int nvalid = min(TILE, N - tile0);

    if (tid < 112) P[tid] = d_P[l][tid];

    const size_t gbase4 = ((size_t)l * N + tile0) * 4;   // float4 units
    const float4* gin  = reinterpret_cast<const float4*>(state) + gbase4;
    float4*       gout = reinterpret_cast<float4*>(out)   + gbase4;

    // stage in: coalesced cp.async.cg -> swizzled SMEM (no register round-trip)
    #pragma unroll
    for (int k = 0; k < 4; k++) {
        int e = k * TILE + tid;
        int r = e >> 2, c = e & 3;
        if (r < nvalid)
            cp_async16(smem_u32(&buf[r * 4 + (c ^ ((r >> 1) & 3))]), gin + e);
    }
    asm volatile("cp.async.commit_group;");
    asm volatile("cp.async.wait_group 0;" ::: "memory");
    __syncthreads();

    {
        const int r  = tid;
        const int sw = (r >> 1) & 3;
        float4 v0 = buf[r * 4 + (0 ^ sw)];
        float4 v1 = buf[r * 4 + (1 ^ sw)];
        float4 v2 = buf[r * 4 + (2 ^ sw)];
        float4 v3 = buf[r * 4 + (3 ^ sw)];

        const float x0 = v0.x, x1 = v0.y, x2  = v0.z, x3  = v0.w;
        const float x4 = v1.x, x5 = v1.y, x6  = v1.z, x7  = v1.w;
        const float x8 = v2.x, x9 = v2.y, x10 = v2.z, x11 = v2.w;
        const float x12 = v3.x, x13 = v3.y, x14 = v3.z;   // x15 unused

        const float4* P4 = reinterpret_cast<const float4*>(P);

        // grade-1 block
        float4 a0 = P4[0], a1 = P4[1], a2 = P4[2], a3 = P4[3];
        float y1 = fmaf(x8, a3.x, fmaf(x4, a2.x, fmaf(x2, a1.x, x1 * a0.x)));
        float y2 = fmaf(x8, a3.y, fmaf(x4, a2.y, fmaf(x2, a1.y, x1 * a0.y)));
        float y4 = fmaf(x8, a3.z, fmaf(x4, a2.z, fmaf(x2, a1.z, x1 * a0.z)));
        float y8 = fmaf(x8, a3.w, fmaf(x4, a2.w, fmaf(x2, a1.w, x1 * a0.w)));

        // grade-2 block
        float y3, y5, y6, y9, y10, y12;
        {
            float4 cA = P4[4], cB = P4[5];
            y3 = x3 * cA.x; y5 = x3 * cA.y; y6  = x3 * cA.z;
            y9 = x3 * cA.w; y10 = x3 * cB.x; y12 = x3 * cB.y;
        }
        {
            float4 cA = P4[6], cB = P4[7];
            y3 = fmaf(x5, cA.x, y3); y5  = fmaf(x5, cA.y, y5);  y6  = fmaf(x5, cA.z, y6);
            y9 = fmaf(x5, cA.w, y9); y10 = fmaf(x5, cB.x, y10); y12 = fmaf(x5, cB.y, y12);
        }
        {
            float4 cA = P4[8], cB = P4[9];
            y3 = fmaf(x6, cA.x, y3); y5  = fmaf(x6, cA.y, y5);  y6  = fmaf(x6, cA.z, y6);
            y9 = fmaf(x6, cA.w, y9); y10 = fmaf(x6, cB.x, y10); y12 = fmaf(x6, cB.y, y12);
        }
        {
            float4 cA = P4[10], cB = P4[11];
            y3 = fmaf(x9, cA.x, y3); y5  = fmaf(x9, cA.y, y5);  y6  = fmaf(x9, cA.z, y6);
            y9 = fmaf(x9, cA.w, y9); y10 = fmaf(x9, cB.x, y10); y12 = fmaf(x9, cB.y, y12);
        }
        {
            float4 cA = P4[12], cB = P4[13];
            y3 = fmaf(x10, cA.x, y3); y5  = fmaf(x10, cA.y, y5);  y6  = fmaf(x10, cA.z, y6);
            y9 = fmaf(x10, cA.w, y9); y10 = fmaf(x10, cB.x, y10); y12 = fmaf(x10, cB.y, y12);
        }
        {
            float4 cA = P4[14], cB = P4[15];
            y3 = fmaf(x12, cA.x, y3); y5  = fmaf(x12, cA.y, y5);  y6  = fmaf(x12, cA.z, y6);
            y9 = fmaf(x12, cA.w, y9); y10 = fmaf(x12, cB.x, y10); y12 = fmaf(x12, cB.y, y12);
        }

        // grade-3 block
        float4 h0 = P4[16], h1 = P4[17], h2 = P4[18], h3 = P4[19];
        float y7  = fmaf(x14, h3.x, fmaf(x13, h2.x, fmaf(x11, h1.x, x7 * h0.x)));
        float y11 = fmaf(x14, h3.y, fmaf(x13, h2.y, fmaf(x11, h1.y, x7 * h0.y)));
        float y13 = fmaf(x14, h3.z, fmaf(x13, h2.z, fmaf(x11, h1.z, x7 * h0.z)));
        float y14 = fmaf(x14, h3.w, fmaf(x13, h2.w, fmaf(x11, h1.w, x7 * h0.w)));

        // color unit from x0 (y0 == x0: M~M = 1, grade preserved).
        // bc/b0 read as broadcast scalar LDS inside the loop (saves ~18 regs).
        float raw = x0 * 9.0f;
        float cc = fminf(fmaxf(rintf(raw), 0.0f), 9.0f);
        float dm = raw - cc;
        float m = -4.0f * dm * dm;                  // exact max of the 10 logits
        float se = 0.0f, nc = 0.0f, n0 = 0.0f;
        #pragma unroll
        for (int i = 0; i < 10; i++) {
            float t = raw - (float)i;
            float e = __expf(fmaf(-4.0f * t, t, -m));
            se += e;
            nc = fmaf(e, P[80 + i], nc);
            n0 = fmaf(e, P[96 + i], n0);
        }
        float inv = 1.0f / se;
        float out0  = nc * inv * (1.0f / 9.0f);
        float out15 = 1.0f - n0 * inv;

        // write own row back (exclusive ownership: no barrier needed here)
        buf[r * 4 + (0 ^ sw)] = make_float4(out0, y1,  y2,  y3);
        buf[r * 4 + (1 ^ sw)] = make_float4(y4,   y5,  y6,  y7);
        buf[r * 4 + (2 ^ sw)] = make_float4(y8,   y9,  y10, y11);
        buf[r * 4 + (3 ^ sw)] = make_float4(y12,  y13, y14, out15);
    }
    __syncthreads();

    // stage out: swizzled LDS -> coalesced streaming STG
    #pragma unroll
    for (int k = 0; k < 4; k++) {
        int e = k * TILE + tid;
        int r = e >> 2, c = e & 3;
        if (r < nvalid)
            __stcs(gout + e, buf[r * 4 + (c ^ ((r >> 1) & 3))]);
    }
}

extern "C" void kernel_launch(void* const* d_in, const int* in_sizes, int n_in,
                              void* d_out, int out_size)
{
    const float* state = (const float*)d_in[0];
    const float* instr = (const float*)d_in[1];
    const float* remap = (const float*)d_in[2];
    const float* selw  = (const float*)d_in[3];
    const float* selb  = (const float*)d_in[4];
    float* out = (float*)d_out;

    const int N = in_sizes[0] / (LBATCH * DMV);   // 100000

    setup_kernel<<<LBATCH, 256>>>(instr, remap, selw, selb);

    dim3 grid((N + TILE - 1) / TILE, LBATCH);
    sandwich_color_kernel<<<grid, 256>>>(state, out, N);
}